// round 12
// baseline (speedup 1.0000x reference)
#include <cuda_runtime.h>

// Problem constants
#define BSZ    64
#define NRAYS  131072          // B*H*W = 2*256*256
#define NBLK   (NRAYS / BSZ)   // 2048
#define HW     65536
#define F_OFF  393216          // B*3*HW
#define D_OFF  786432          // 2*B*3*HW
#define STEP   (1.9f / 63.0f)
#define BIGF   3.0e38f

__device__ float g_rayd[NRAYS];
__device__ float g_pmin[NBLK];
__device__ float g_pmax[NBLK];
__device__ float g_mm[2];      // {min, 1/(max-min)}

__device__ __forceinline__ float tanh_fast(float x) {
    float y;
    asm("tanh.approx.f32 %0, %1;" : "=f"(y) : "f"(x));
    return y;
}

#define PACK2(out, lo, hi) \
    asm("mov.b64 %0, {%1, %2};" : "=l"(out) : "f"(lo), "f"(hi))
#define UNPACK2(lo, hi, in) \
    asm("mov.b64 {%0, %1}, %2;" : "=f"(lo), "=f"(hi) : "l"(in))
#define FMA2(out, a, b, c) \
    asm("fma.rn.f32x2 %0, %1, %2, %3;" : "=l"(out) : "l"(a), "l"(b), "l"(c))

// One merged-march sample step.
// u = T/2; w = u*(1+t0); T' = T*(1-op) -> u' = u - w/2 (single fma).
#define SAMP(d)                                              \
    do {                                                     \
        float _d = (d);                                      \
        unsigned long long D2, G01, G23;                     \
        PACK2(D2, _d, _d);                                   \
        FMA2(G01, D2, SH01, BH01);                           \
        FMA2(G23, D2, SH23, BH23);                           \
        float g0, g1, g2, g3;                                \
        UNPACK2(g0, g1, G01);                                \
        UNPACK2(g2, g3, G23);                                \
        float t0 = tanh_fast(g0);                            \
        float t1 = tanh_fast(g1);                            \
        float t2 = tanh_fast(g2);                            \
        float t3 = tanh_fast(g3);                            \
        float w  = fmaf(u3, t0, u3);                         \
        u3 = fmaf(-0.5f, w, u3);                             \
        F0 = fmaf(w, t1, F0);                                \
        F1 = fmaf(w, t2, F1);                                \
        F2 = fmaf(w, t3, F2);                                \
        accd = fmaf(w, _d, accd);                            \
    } while (0)

__global__ void __launch_bounds__(BSZ) nerf_main(
    const float* __restrict__ tm,   // transform_matrix (2,3,4)
    const float* __restrict__ Wq,   // W_query (6,4)
    float* __restrict__ out)
{
    // Fine midpoints, per-thread column (stride BSZ, conflict-free).
    // 65 rows: row 64 is a pad so the uniform merge can over-read safely.
    __shared__ float buf[65 * BSZ];
    const int tid = threadIdx.x;
    const int r  = blockIdx.x * BSZ + tid;
    const int b  = r >> 16;
    const int n  = r & 65535;
    const int pi = n >> 8;
    const int pj = n & 255;

    float xv = 1.0f - (float)pj * (2.0f / 255.0f); if (pj == 255) xv = -1.0f;
    float yv = 1.0f - (float)pi * (2.0f / 255.0f); if (pi == 255) yv = -1.0f;
    float cx = xv / 4.2f;
    float cy = yv / 4.2f;

    const float* M = tm + b * 12;
    float ddx = M[0]*cx + M[1]*cy + M[2];
    float ddy = M[4]*cx + M[5]*cy + M[6];
    float ddz = M[8]*cx + M[9]*cy + M[10];
    float ox = M[3], oy = M[7], oz = M[11];

    // feat(d) = base + d*slope; pre-scaled by 0.5: sigmoid = 0.5*tanh(arg)+0.5
    float bh[4], sh[4];
    #pragma unroll
    for (int c = 0; c < 4; c++) {
        float w0 = Wq[c], w1 = Wq[4+c], w2 = Wq[8+c];
        float w3 = Wq[12+c], w4 = Wq[16+c], w5 = Wq[20+c];
        sh[c] = 0.5f * (ddx*w0 + ddy*w1 + ddz*w2);
        bh[c] = 0.5f * (ox*w0 + oy*w1 + oz*w2 + ddx*w3 + ddy*w4 + ddz*w5);
    }
    unsigned long long SH01, SH23, BH01, BH23;
    PACK2(SH01, sh[0], sh[1]);
    PACK2(SH23, sh[2], sh[3]);
    PACK2(BH01, bh[0], bh[1]);
    PACK2(BH23, bh[2], bh[3]);
    const float sh0 = sh[0], bh0 = bh[0];

    float* outp = out + b * (3 * HW) + n;

    // ---- Pass 1: coarse march (uniform control flow) ----
    float u1 = 0.5f, A0 = 0.f, A1 = 0.f, A2 = 0.f, cc1 = 0.f;
    {
        float dcur = 0.1f;
        #pragma unroll 16
        for (int p = 0; p < 64; p++) {
            float d  = (p == 63) ? 2.0f : dcur;
            unsigned long long D2, G01, G23;
            PACK2(D2, d, d);
            FMA2(G01, D2, SH01, BH01);
            FMA2(G23, D2, SH23, BH23);
            float g0, g1, g2, g3;
            UNPACK2(g0, g1, G01);
            UNPACK2(g2, g3, G23);
            float t0 = tanh_fast(g0);
            float t1 = tanh_fast(g1);
            float t2 = tanh_fast(g2);
            float t3 = tanh_fast(g3);
            float w  = fmaf(u1, t0, u1);
            u1 = fmaf(-0.5f, w, u1);
            A0 = fmaf(w, t1, A0);
            A1 = fmaf(w, t2, A1);
            A2 = fmaf(w, t3, A2);
            cc1 += w + 1e-5f;
            dcur += STEP;
        }
    }
    const float s = cc1;                       // total of wpad
    // Store coarse image now (retire A0-2 + address registers early).
    {
        const float h1 = 0.5f - u1;
        outp[0]      = fmaf(0.5f, A0, h1);
        outp[HW]     = fmaf(0.5f, A1, h1);
        outp[2 * HW] = fmaf(0.5f, A2, h1);
    }

    // ---- Pass 2: inverse-CDF producer -> fine midpoints into smem ----
    // Coarse cumsum regenerated via identical t0 recurrence (bitwise-equal
    // to pass 1's w sequence). searchsorted(cdf, u, 'right') streamed.
    {
        const float su = s * (1.0f / 64.0f);
        float u2 = 0.5f, cc = 0.0f;
        float cprev = 0.0f, prevbin = 0.0f, dprev = 0.1f;
        float us = 0.0f;                       // u_k * s, incremental
        float dcur = 0.1f;
        int k = 0;
        int waddr = tid;
        #pragma unroll 1
        for (int p = 0; p < 64; p++) {
            float d  = (p == 63) ? 2.0f : dcur;
            float t0 = tanh_fast(fmaf(d, sh0, bh0));
            float w  = fmaf(u2, t0, u2);
            u2 = fmaf(-0.5f, w, u2);
            cc += w + 1e-5f;
            while (k <= 64 && us < cc) {       // ind == p (side='right')
                float bin;
                if (p == 0) {
                    bin = 0.1f;
                } else {
                    float t = __fdividef(us - cprev, cc - cprev);
                    t = fminf(fmaxf(t, 0.0f), 1.0f);
                    bin = fmaf(t, d - dprev, dprev);
                }
                if (k > 0) { buf[waddr] = 0.5f * (prevbin + bin); waddr += BSZ; }
                prevbin = bin;
                k++;
                us += su;
            }
            cprev = cc;
            dprev = d;
            dcur += STEP;
        }
        while (k <= 64) {                      // ind == 64 -> depth[63] = FAR
            float bin = 2.0f;
            if (k > 0) { buf[waddr] = 0.5f * (prevbin + bin); waddr += BSZ; }
            prevbin = bin;
            k++;
        }
    }
    // No sync needed: each thread reads only its own column.

    // ---- Pass 3: merged march — UNIFORM 128-iteration 2-pointer merge ----
    // All threads run exactly 128 iterations; coarse/fine select is
    // predication, no divergent sub-loops. Coarse-first on ties == stable sort.
    float u3 = 0.5f, F0 = 0.f, F1 = 0.f, F2 = 0.f, accd = 0.f;
    {
        int pc = 0, pf = 0;
        int faddr = tid;
        float dc = 0.1f;
        float df = buf[faddr];
        #pragma unroll 4
        for (int m = 0; m < 128; m++) {
            bool cf = (dc <= df);
            float d = cf ? dc : df;
            SAMP(d);
            if (cf) {
                pc++;
                dc = (pc == 63) ? 2.0f : ((pc >= 64) ? BIGF : dc + STEP);
            } else {
                pf++;
                faddr += BSZ;                  // row 64 = pad row (in-bounds)
            }
            float ld = buf[faddr];
            df = (pf < 64) ? ld : BIGF;
        }
    }
    const float fsum = 1.0f - 2.0f * u3;       // Sum(w) over merged march
    const float h3 = 0.5f - u3;
    outp[F_OFF]          = fmaf(0.5f, F0, h3);
    outp[F_OFF + HW]     = fmaf(0.5f, F1, h3);
    outp[F_OFF + 2 * HW] = fmaf(0.5f, F2, h3);
    float fop  = fminf(fsum, 1.0f);
    float rayd = accd + (1.0f - fop) * 2.0f;   // d_all.max() == FAR globally
    g_rayd[r] = rayd;

    // ---- block min/max partials (2 warps) ----
    float mn = rayd, mx = rayd;
    #pragma unroll
    for (int o = 16; o; o >>= 1) {
        mn = fminf(mn, __shfl_xor_sync(0xffffffffu, mn, o));
        mx = fmaxf(mx, __shfl_xor_sync(0xffffffffu, mx, o));
    }
    __shared__ float smn[2], smx[2];
    if ((tid & 31) == 0) { smn[tid >> 5] = mn; smx[tid >> 5] = mx; }
    __syncthreads();
    if (tid == 0) {
        g_pmin[blockIdx.x] = fminf(mn, smn[1]);
        g_pmax[blockIdx.x] = fmaxf(mx, smx[1]);
    }
}

// One-block global min/max over the 2048 partials; writes {min, 1/(max-min)}.
__global__ void __launch_bounds__(1024) nerf_reduce()
{
    const int t = threadIdx.x;
    float mn = fminf(g_pmin[t], g_pmin[t + 1024]);
    float mx = fmaxf(g_pmax[t], g_pmax[t + 1024]);
    #pragma unroll
    for (int o = 16; o; o >>= 1) {
        mn = fminf(mn, __shfl_xor_sync(0xffffffffu, mn, o));
        mx = fmaxf(mx, __shfl_xor_sync(0xffffffffu, mx, o));
    }
    __shared__ float smn[32], smx[32];
    if ((t & 31) == 0) { smn[t >> 5] = mn; smx[t >> 5] = mx; }
    __syncthreads();
    if (t < 32) {
        mn = smn[t];
        mx = smx[t];
        #pragma unroll
        for (int o = 16; o; o >>= 1) {
            mn = fminf(mn, __shfl_xor_sync(0xffffffffu, mn, o));
            mx = fmaxf(mx, __shfl_xor_sync(0xffffffffu, mx, o));
        }
        if (t == 0) { g_mm[0] = mn; g_mm[1] = 1.0f / (mx - mn); }
    }
}

// Vectorized normalize: 32768 threads x float4.
__global__ void __launch_bounds__(512) nerf_norm(float* __restrict__ out)
{
    const int i = blockIdx.x * 512 + threadIdx.x;
    const float mn = g_mm[0];
    const float sc = g_mm[1];
    float4 v = reinterpret_cast<const float4*>(g_rayd)[i];
    float4 o;
    o.x = (v.x - mn) * sc;
    o.y = (v.y - mn) * sc;
    o.z = (v.z - mn) * sc;
    o.w = (v.w - mn) * sc;
    reinterpret_cast<float4*>(out + D_OFF)[i] = o;
}

extern "C" void kernel_launch(void* const* d_in, const int* in_sizes, int n_in,
                              void* d_out, int out_size)
{
    const float* tm = (const float*)d_in[0];   // transform_matrix (2,3,4)
    const float* Wq = (const float*)d_in[1];   // W_query (6,4)
    float* out = (float*)d_out;

    nerf_main<<<NBLK, BSZ>>>(tm, Wq, out);
    nerf_reduce<<<1, 1024>>>();
    nerf_norm<<<NRAYS / 4 / 512, 512>>>(out);
}

// round 13
// speedup vs baseline: 1.1233x; 1.1233x over previous
#include <cuda_runtime.h>

// Problem constants
#define BSZ    64
#define NRAYS  131072          // B*H*W = 2*256*256
#define NBLK   (NRAYS / BSZ)   // 2048
#define HW     65536
#define F_OFF  393216          // B*3*HW
#define D_OFF  786432          // 2*B*3*HW
#define STEP   (1.9f / 63.0f)

__device__ float g_rayd[NRAYS];
__device__ unsigned g_amin = 0x7f800000u;   // +INF bits (positive-float order == uint order)
__device__ unsigned g_amax = 0u;
__device__ unsigned g_done = 0u;
__device__ float g_mm[2];                   // {min, 1/(max-min)}

__device__ __forceinline__ float tanh_fast(float x) {
    float y;
    asm("tanh.approx.f32 %0, %1;" : "=f"(y) : "f"(x));
    return y;
}

#define PACK2(out, lo, hi) \
    asm("mov.b64 %0, {%1, %2};" : "=l"(out) : "f"(lo), "f"(hi))
#define UNPACK2(lo, hi, in) \
    asm("mov.b64 {%0, %1}, %2;" : "=f"(lo), "=f"(hi) : "l"(in))
#define FMA2(out, a, b, c) \
    asm("fma.rn.f32x2 %0, %1, %2, %3;" : "=l"(out) : "l"(a), "l"(b), "l"(c))

// One merged-march sample step.
// u = T/2; w = u*(1+t0); T' = T*(1-op) -> u' = u - w/2 (single fma).
#define SAMP(d)                                              \
    do {                                                     \
        float _d = (d);                                      \
        unsigned long long D2, G01, G23;                     \
        PACK2(D2, _d, _d);                                   \
        FMA2(G01, D2, SH01, BH01);                           \
        FMA2(G23, D2, SH23, BH23);                           \
        float g0, g1, g2, g3;                                \
        UNPACK2(g0, g1, G01);                                \
        UNPACK2(g2, g3, G23);                                \
        float t0 = tanh_fast(g0);                            \
        float t1 = tanh_fast(g1);                            \
        float t2 = tanh_fast(g2);                            \
        float t3 = tanh_fast(g3);                            \
        float w  = fmaf(u3, t0, u3);                         \
        u3 = fmaf(-0.5f, w, u3);                             \
        F0 = fmaf(w, t1, F0);                                \
        F1 = fmaf(w, t2, F1);                                \
        F2 = fmaf(w, t3, F2);                                \
        accd = fmaf(w, _d, accd);                            \
    } while (0)

// Emit all coarse samples with depth <= lim
#define DRAIN_COARSE(lim)                                    \
    while (pc < 64 && dc <= (lim)) {                         \
        SAMP(dc);                                            \
        pc++;                                                \
        dc = (pc == 63) ? 2.0f : dc + STEP;                  \
    }

__global__ void __launch_bounds__(BSZ, 16) nerf_main(
    const float* __restrict__ tm,   // transform_matrix (2,3,4)
    const float* __restrict__ Wq,   // W_query (6,4)
    float* __restrict__ out)
{
    const int tid = threadIdx.x;
    const int r  = blockIdx.x * BSZ + tid;
    const int b  = r >> 16;
    const int n  = r & 65535;
    const int pi = n >> 8;
    const int pj = n & 255;

    float xv = 1.0f - (float)pj * (2.0f / 255.0f); if (pj == 255) xv = -1.0f;
    float yv = 1.0f - (float)pi * (2.0f / 255.0f); if (pi == 255) yv = -1.0f;
    float cx = xv / 4.2f;
    float cy = yv / 4.2f;

    const float* M = tm + b * 12;
    float ddx = M[0]*cx + M[1]*cy + M[2];
    float ddy = M[4]*cx + M[5]*cy + M[6];
    float ddz = M[8]*cx + M[9]*cy + M[10];
    float ox = M[3], oy = M[7], oz = M[11];

    // feat(d) = base + d*slope; pre-scaled by 0.5: sigmoid = 0.5*tanh(arg)+0.5
    float bh[4], sh[4];
    #pragma unroll
    for (int c = 0; c < 4; c++) {
        float w0 = Wq[c], w1 = Wq[4+c], w2 = Wq[8+c];
        float w3 = Wq[12+c], w4 = Wq[16+c], w5 = Wq[20+c];
        sh[c] = 0.5f * (ddx*w0 + ddy*w1 + ddz*w2);
        bh[c] = 0.5f * (ox*w0 + oy*w1 + oz*w2 + ddx*w3 + ddy*w4 + ddz*w5);
    }
    unsigned long long SH01, SH23, BH01, BH23;
    PACK2(SH01, sh[0], sh[1]);
    PACK2(SH23, sh[2], sh[3]);
    PACK2(BH01, bh[0], bh[1]);
    PACK2(BH23, bh[2], bh[3]);
    const float sh0 = sh[0], bh0 = bh[0];

    float* outp = out + b * (3 * HW) + n;

    // ---- Pass 1: coarse march (no stores; cumsum recomputed later) ----
    float u1 = 0.5f, A0 = 0.f, A1 = 0.f, A2 = 0.f, cc1 = 0.f;
    {
        float dcur = 0.1f;
        #pragma unroll 16
        for (int p = 0; p < 64; p++) {
            float d  = (p == 63) ? 2.0f : dcur;
            unsigned long long D2, G01, G23;
            PACK2(D2, d, d);
            FMA2(G01, D2, SH01, BH01);
            FMA2(G23, D2, SH23, BH23);
            float g0, g1, g2, g3;
            UNPACK2(g0, g1, G01);
            UNPACK2(g2, g3, G23);
            float t0 = tanh_fast(g0);
            float t1 = tanh_fast(g1);
            float t2 = tanh_fast(g2);
            float t3 = tanh_fast(g3);
            float w  = fmaf(u1, t0, u1);
            u1 = fmaf(-0.5f, w, u1);
            A0 = fmaf(w, t1, A0);
            A1 = fmaf(w, t2, A1);
            A2 = fmaf(w, t3, A2);
            cc1 += w + 1e-5f;
            dcur += STEP;
        }
    }
    const float s = cc1;                       // total of wpad
    // Sum(w) = 1 - T = 1 - 2*u1; a = 0.5*(A + Sum(w)).
    // Store coarse image NOW to retire registers early.
    {
        const float h1 = 0.5f - u1;
        outp[0]      = fmaf(0.5f, A0, h1);
        outp[HW]     = fmaf(0.5f, A1, h1);
        outp[2 * HW] = fmaf(0.5f, A2, h1);
    }

    // ---- Pass 2+3 fused: inverse-CDF sampling feeding the merged march ----
    // searchsorted(cumsum(wpad)/s, u, 'right') == searchsorted(cumsum(wpad), u*s)
    // Coarse cumsum REGENERATED via identical t0-only recurrence (bitwise-equal
    // to pass 1's w sequence) -> no shared-memory buffer. Fine midpoints emerge
    // sorted; consume each immediately, draining pending coarse samples first
    // (coarse-first on ties == stable sort).
    float u3 = 0.5f, F0 = 0.f, F1 = 0.f, F2 = 0.f, accd = 0.f;
    {
        const float su = s * (1.0f / 64.0f);
        float u2 = 0.5f;                       // cumsum regeneration recurrence
        float cc = 0.0f;
        float cprev = 0.0f, prevbin = 0.0f, dprev = 0.1f;
        float us = 0.0f;                       // u_k * s, incremental
        float dcur = 0.1f;                     // CDF-bin depth walker
        float dc = 0.1f;                       // march coarse depth walker
        int k = 0, pc = 0;
        #pragma unroll 1
        for (int p = 0; p < 64; p++) {
            float d  = (p == 63) ? 2.0f : dcur;
            {   // regenerate w_p exactly as in pass 1
                float t0 = tanh_fast(fmaf(d, sh0, bh0));
                float w  = fmaf(u2, t0, u2);
                u2 = fmaf(-0.5f, w, u2);
                cc += w + 1e-5f;
            }
            while (k <= 64 && us < cc) {       // ind == p (side='right')
                float bin;
                if (p == 0) {
                    bin = 0.1f;
                } else {
                    float t = __fdividef(us - cprev, cc - cprev);
                    t = fminf(fmaxf(t, 0.0f), 1.0f);
                    bin = fmaf(t, d - dprev, dprev);
                }
                if (k > 0) {
                    float m = 0.5f * (prevbin + bin);  // fine midpoint (sorted)
                    DRAIN_COARSE(m);
                    SAMP(m);
                }
                prevbin = bin;
                k++;
                us += su;
            }
            cprev = cc;
            dprev = d;
            dcur += STEP;
        }
        while (k <= 64) {                      // ind == 64 -> depth[63] = FAR
            float bin = 2.0f;
            if (k > 0) {
                float m = 0.5f * (prevbin + bin);
                DRAIN_COARSE(m);
                SAMP(m);
            }
            prevbin = bin;
            k++;
        }
        DRAIN_COARSE(3.0e38f);                 // flush remaining coarse
    }
    const float fsum = 1.0f - 2.0f * u3;       // Sum(w) over merged march
    const float h3 = 0.5f - u3;
    outp[F_OFF]          = fmaf(0.5f, F0, h3);
    outp[F_OFF + HW]     = fmaf(0.5f, F1, h3);
    outp[F_OFF + 2 * HW] = fmaf(0.5f, F2, h3);
    float fop  = fminf(fsum, 1.0f);
    float rayd = accd + (1.0f - fop) * 2.0f;   // d_all.max() == FAR globally
    g_rayd[r] = rayd;

    // ---- block min/max -> global atomics (rayd >= 0: uint order == float order)
    float mn = rayd, mx = rayd;
    #pragma unroll
    for (int o = 16; o; o >>= 1) {
        mn = fminf(mn, __shfl_xor_sync(0xffffffffu, mn, o));
        mx = fmaxf(mx, __shfl_xor_sync(0xffffffffu, mx, o));
    }
    __shared__ float smn[2], smx[2];
    if ((tid & 31) == 0) { smn[tid >> 5] = mn; smx[tid >> 5] = mx; }
    __syncthreads();
    if (tid == 0) {
        mn = fminf(mn, smn[1]);
        mx = fmaxf(mx, smx[1]);
        atomicMin(&g_amin, __float_as_uint(mn));
        atomicMax(&g_amax, __float_as_uint(mx));
        __threadfence();
        unsigned done = atomicAdd(&g_done, 1u);
        if (done == NBLK - 1) {                // last block finalizes
            float lo = __uint_as_float(g_amin);
            float hi = __uint_as_float(g_amax);
            g_mm[0] = lo;
            g_mm[1] = 1.0f / (hi - lo);
            // reset for next graph replay (deterministic across launches)
            g_amin = 0x7f800000u;
            g_amax = 0u;
            __threadfence();
            g_done = 0u;
        }
    }
}

// Vectorized normalize: 32768 threads x float4.
__global__ void __launch_bounds__(512) nerf_norm(float* __restrict__ out)
{
    const int i = blockIdx.x * 512 + threadIdx.x;
    const float mn = g_mm[0];
    const float sc = g_mm[1];
    float4 v = reinterpret_cast<const float4*>(g_rayd)[i];
    float4 o;
    o.x = (v.x - mn) * sc;
    o.y = (v.y - mn) * sc;
    o.z = (v.z - mn) * sc;
    o.w = (v.w - mn) * sc;
    reinterpret_cast<float4*>(out + D_OFF)[i] = o;
}

extern "C" void kernel_launch(void* const* d_in, const int* in_sizes, int n_in,
                              void* d_out, int out_size)
{
    const float* tm = (const float*)d_in[0];   // transform_matrix (2,3,4)
    const float* Wq = (const float*)d_in[1];   // W_query (6,4)
    float* out = (float*)d_out;

    nerf_main<<<NBLK, BSZ>>>(tm, Wq, out);
    nerf_norm<<<NRAYS / 4 / 512, 512>>>(out);
}

// round 15
// speedup vs baseline: 1.1436x; 1.0180x over previous
#include <cuda_runtime.h>

// Problem constants
#define BSZ    64
#define NRAYS  131072          // B*H*W = 2*256*256
#define NBLK   (NRAYS / BSZ)   // 2048
#define HW     65536
#define F_OFF  393216          // B*3*HW
#define D_OFF  786432          // 2*B*3*HW
#define STEP   (1.9f / 63.0f)

__device__ float g_rayd[NRAYS];
__device__ unsigned g_amin = 0x7f800000u;   // +INF bits (positive-float order == uint order)
__device__ unsigned g_amax = 0u;
__device__ unsigned g_done = 0u;
__device__ float g_mm[2];                   // {min, 1/(max-min)}

__device__ __forceinline__ float tanh_fast(float x) {
    float y;
    asm("tanh.approx.f32 %0, %1;" : "=f"(y) : "f"(x));
    return y;
}

#define PACK2(out, lo, hi) \
    asm("mov.b64 %0, {%1, %2};" : "=l"(out) : "f"(lo), "f"(hi))
#define UNPACK2(lo, hi, in) \
    asm("mov.b64 {%0, %1}, %2;" : "=f"(lo), "=f"(hi) : "l"(in))
#define FMA2(out, a, b, c) \
    asm("fma.rn.f32x2 %0, %1, %2, %3;" : "=l"(out) : "l"(a), "l"(b), "l"(c))

// One merged-march sample step.
// u = T/2; w = u*(1+t0); T' = T*(1-op) -> u' = u - w/2 (single fma).
#define SAMP(d)                                              \
    do {                                                     \
        float _d = (d);                                      \
        unsigned long long D2, G01, G23;                     \
        PACK2(D2, _d, _d);                                   \
        FMA2(G01, D2, SH01, BH01);                           \
        FMA2(G23, D2, SH23, BH23);                           \
        float g0, g1, g2, g3;                                \
        UNPACK2(g0, g1, G01);                                \
        UNPACK2(g2, g3, G23);                                \
        float t0 = tanh_fast(g0);                            \
        float t1 = tanh_fast(g1);                            \
        float t2 = tanh_fast(g2);                            \
        float t3 = tanh_fast(g3);                            \
        float w  = fmaf(u3, t0, u3);                         \
        u3 = fmaf(-0.5f, w, u3);                             \
        F0 = fmaf(w, t1, F0);                                \
        F1 = fmaf(w, t2, F1);                                \
        F2 = fmaf(w, t3, F2);                                \
        accd = fmaf(w, _d, accd);                            \
    } while (0)

// Emit all coarse samples with depth <= lim
#define DRAIN_COARSE(lim)                                    \
    while (pc < 64 && dc <= (lim)) {                         \
        SAMP(dc);                                            \
        pc++;                                                \
        dc = (pc == 63) ? 2.0f : dc + STEP;                  \
    }

__global__ void __launch_bounds__(BSZ, 16) nerf_main(
    const float* __restrict__ tm,   // transform_matrix (2,3,4)
    const float* __restrict__ Wq,   // W_query (6,4)
    float* __restrict__ out)
{
    const int tid = threadIdx.x;
    const int r  = blockIdx.x * BSZ + tid;
    const int b  = r >> 16;
    const int n  = r & 65535;
    const int pi = n >> 8;
    const int pj = n & 255;

    float xv = 1.0f - (float)pj * (2.0f / 255.0f); if (pj == 255) xv = -1.0f;
    float yv = 1.0f - (float)pi * (2.0f / 255.0f); if (pi == 255) yv = -1.0f;
    float cx = xv / 4.2f;
    float cy = yv / 4.2f;

    const float* M = tm + b * 12;
    float ddx = M[0]*cx + M[1]*cy + M[2];
    float ddy = M[4]*cx + M[5]*cy + M[6];
    float ddz = M[8]*cx + M[9]*cy + M[10];
    float ox = M[3], oy = M[7], oz = M[11];

    // feat(d) = base + d*slope; pre-scaled by 0.5: sigmoid = 0.5*tanh(arg)+0.5
    float bh[4], sh[4];
    #pragma unroll
    for (int c = 0; c < 4; c++) {
        float w0 = Wq[c], w1 = Wq[4+c], w2 = Wq[8+c];
        float w3 = Wq[12+c], w4 = Wq[16+c], w5 = Wq[20+c];
        sh[c] = 0.5f * (ddx*w0 + ddy*w1 + ddz*w2);
        bh[c] = 0.5f * (ox*w0 + oy*w1 + oz*w2 + ddx*w3 + ddy*w4 + ddz*w5);
    }
    unsigned long long SH01, SH23, BH01, BH23;
    PACK2(SH01, sh[0], sh[1]);
    PACK2(SH23, sh[2], sh[3]);
    PACK2(BH01, bh[0], bh[1]);
    PACK2(BH23, bh[2], bh[3]);
    const float sh0 = sh[0], bh0 = bh[0];

    float* outp = out + b * (3 * HW) + n;

    // ---- Pass 1: coarse march (no stores; cumsum recomputed later) ----
    float u1 = 0.5f, A0 = 0.f, A1 = 0.f, A2 = 0.f, cc1 = 0.f;
    {
        float dcur = 0.1f;
        #pragma unroll 16
        for (int p = 0; p < 64; p++) {
            float d  = (p == 63) ? 2.0f : dcur;
            unsigned long long D2, G01, G23;
            PACK2(D2, d, d);
            FMA2(G01, D2, SH01, BH01);
            FMA2(G23, D2, SH23, BH23);
            float g0, g1, g2, g3;
            UNPACK2(g0, g1, G01);
            UNPACK2(g2, g3, G23);
            float t0 = tanh_fast(g0);
            float t1 = tanh_fast(g1);
            float t2 = tanh_fast(g2);
            float t3 = tanh_fast(g3);
            float w  = fmaf(u1, t0, u1);
            u1 = fmaf(-0.5f, w, u1);
            A0 = fmaf(w, t1, A0);
            A1 = fmaf(w, t2, A1);
            A2 = fmaf(w, t3, A2);
            cc1 += w + 1e-5f;
            dcur += STEP;
        }
    }
    const float s = cc1;                       // total of wpad
    // Sum(w) = 1 - T = 1 - 2*u1; a = 0.5*(A + Sum(w)).
    // Store coarse image NOW to retire registers early.
    {
        const float h1 = 0.5f - u1;
        outp[0]      = fmaf(0.5f, A0, h1);
        outp[HW]     = fmaf(0.5f, A1, h1);
        outp[2 * HW] = fmaf(0.5f, A2, h1);
    }

    // ---- Pass 2+3 fused: inverse-CDF sampling feeding the merged march ----
    // searchsorted(cumsum(wpad)/s, u, 'right') == searchsorted(cumsum(wpad), u*s)
    // Coarse cumsum REGENERATED via identical t0-only recurrence (bitwise-equal
    // to pass 1's w sequence) -> no shared-memory buffer. Fine midpoints emerge
    // sorted; consume each immediately, draining pending coarse samples first
    // (coarse-first on ties == stable sort).
    float u3 = 0.5f, F0 = 0.f, F1 = 0.f, F2 = 0.f, accd = 0.f;
    {
        const float su = s * (1.0f / 64.0f);
        float u2 = 0.5f;                       // cumsum regeneration recurrence
        float cc = 0.0f;
        float cprev = 0.0f, prevbin = 0.0f, dprev = 0.1f;
        float us = 0.0f;                       // u_k * s, incremental
        float dcur = 0.1f;                     // CDF-bin depth walker
        float dc = 0.1f;                       // march coarse depth walker
        int k = 0, pc = 0;

        // ---- peeled p = 0: every emitted bin == NEAR (0.1) ----
        {
            float t0 = tanh_fast(fmaf(0.1f, sh0, bh0));
            float w  = fmaf(u2, t0, u2);
            u2 = fmaf(-0.5f, w, u2);
            cc += w + 1e-5f;
            while (k <= 64 && us < cc) {       // ind == 0 -> bin = depth[0]
                if (k > 0) {
                    // m = 0.5*(0.1+0.1) = 0.1; coarse p=0 (dc=0.1) drains first
                    DRAIN_COARSE(0.1f);
                    SAMP(0.1f);
                }
                k++;
                us += su;
            }
            prevbin = 0.1f;
            cprev = cc;
            dcur += STEP;
        }

        #pragma unroll 1
        for (int p = 1; p < 64; p++) {
            float d  = (p == 63) ? 2.0f : dcur;
            {   // regenerate w_p exactly as in pass 1
                float t0 = tanh_fast(fmaf(d, sh0, bh0));
                float w  = fmaf(u2, t0, u2);
                u2 = fmaf(-0.5f, w, u2);
                cc += w + 1e-5f;
            }
            while (k <= 64 && us < cc) {       // ind == p (side='right')
                float t = __fdividef(us - cprev, cc - cprev);
                t = fminf(fmaxf(t, 0.0f), 1.0f);
                float bin = fmaf(t, d - dprev, dprev);
                if (k > 0) {
                    float m = 0.5f * (prevbin + bin);  // fine midpoint (sorted)
                    DRAIN_COARSE(m);
                    SAMP(m);
                }
                prevbin = bin;
                k++;
                us += su;
            }
            cprev = cc;
            dprev = d;
            dcur += STEP;
        }
        while (k <= 64) {                      // ind == 64 -> depth[63] = FAR
            float bin = 2.0f;
            if (k > 0) {
                float m = 0.5f * (prevbin + bin);
                DRAIN_COARSE(m);
                SAMP(m);
            }
            prevbin = bin;
            k++;
        }
        DRAIN_COARSE(3.0e38f);                 // flush remaining coarse
    }
    const float fsum = 1.0f - 2.0f * u3;       // Sum(w) over merged march
    const float h3 = 0.5f - u3;
    outp[F_OFF]          = fmaf(0.5f, F0, h3);
    outp[F_OFF + HW]     = fmaf(0.5f, F1, h3);
    outp[F_OFF + 2 * HW] = fmaf(0.5f, F2, h3);
    float fop  = fminf(fsum, 1.0f);
    float rayd = accd + (1.0f - fop) * 2.0f;   // d_all.max() == FAR globally
    g_rayd[r] = rayd;

    // ---- block min/max -> global atomics (rayd >= 0: uint order == float order)
    float mn = rayd, mx = rayd;
    #pragma unroll
    for (int o = 16; o; o >>= 1) {
        mn = fminf(mn, __shfl_xor_sync(0xffffffffu, mn, o));
        mx = fmaxf(mx, __shfl_xor_sync(0xffffffffu, mx, o));
    }
    __shared__ float smn[2], smx[2];
    if ((tid & 31) == 0) { smn[tid >> 5] = mn; smx[tid >> 5] = mx; }
    __syncthreads();
    if (tid == 0) {
        mn = fminf(mn, smn[1]);
        mx = fmaxf(mx, smx[1]);
        atomicMin(&g_amin, __float_as_uint(mn));
        atomicMax(&g_amax, __float_as_uint(mx));
        __threadfence();
        unsigned done = atomicAdd(&g_done, 1u);
        if (done == NBLK - 1) {                // last block finalizes
            float lo = __uint_as_float(g_amin);
            float hi = __uint_as_float(g_amax);
            g_mm[0] = lo;
            g_mm[1] = 1.0f / (hi - lo);
            // reset for next graph replay (deterministic across launches)
            g_amin = 0x7f800000u;
            g_amax = 0u;
            __threadfence();
            g_done = 0u;
        }
    }
}

// Vectorized normalize: 256 blocks x 128 threads x float4 (all SMs lit).
__global__ void __launch_bounds__(128) nerf_norm(float* __restrict__ out)
{
    const int i = blockIdx.x * 128 + threadIdx.x;
    const float mn = g_mm[0];
    const float sc = g_mm[1];
    float4 v = reinterpret_cast<const float4*>(g_rayd)[i];
    float4 o;
    o.x = (v.x - mn) * sc;
    o.y = (v.y - mn) * sc;
    o.z = (v.z - mn) * sc;
    o.w = (v.w - mn) * sc;
    reinterpret_cast<float4*>(out + D_OFF)[i] = o;
}

extern "C" void kernel_launch(void* const* d_in, const int* in_sizes, int n_in,
                              void* d_out, int out_size)
{
    const float* tm = (const float*)d_in[0];   // transform_matrix (2,3,4)
    const float* Wq = (const float*)d_in[1];   // W_query (6,4)
    float* out = (float*)d_out;

    nerf_main<<<NBLK, BSZ>>>(tm, Wq, out);
    nerf_norm<<<NRAYS / 4 / 128, 128>>>(out);
}